// round 4
// baseline (speedup 1.0000x reference)
#include <cuda_runtime.h>
#include <cuda_bf16.h>
#include <math.h>

// ---------------- problem constants ----------------
#define B_   2
#define N_   4096
#define D_   1024
#define H_   16
#define DH_  64
#define R_   64
#define L_   6
#define FF_  4096
#define INNER_ 1024
#define M_   (B_*N_)        // 8192 rows
#define EPS_ 1e-5f
#define STAB_ 1e-6f

// ---------------- scratch (static device globals; allowed) ----------------
__device__ __align__(16) float g_qkv[M_ * 3 * INNER_];      // 96 MB
__device__ __align__(16) float g_ff1[M_ * FF_];             // 128 MB
__device__ __align__(16) float g_attnout[M_ * INNER_];      // 32 MB
__device__ __align__(16) float g_kvpart[B_*H_*16*R_*DH_];   // 8 MB
__device__ __align__(16) float g_kspart[B_*H_*16*R_];
__device__ __align__(16) float g_kv[B_*H_*R_*DH_];
__device__ __align__(16) float g_ksum[B_*H_*R_];
__device__ __align__(16) float g_mean[M_];
__device__ __align__(16) float g_rstd[M_];

// ---------------- embedding ----------------
__global__ __launch_bounds__(256) void embed_kernel(
    const int* __restrict__ tokens, const float* __restrict__ te,
    const float* __restrict__ pe, float* __restrict__ x)
{
    int row = blockIdx.x;          // 0..8191
    int tid = threadIdx.x;         // 256 threads -> float4 each
    int n = row & (N_ - 1);
    int tok = tokens[row];
    float4 a = *(const float4*)&te[(size_t)tok * D_ + tid * 4];
    float4 p = *(const float4*)&pe[(size_t)n * D_ + tid * 4];
    a.x += p.x; a.y += p.y; a.z += p.z; a.w += p.w;
    *(float4*)&x[(size_t)row * D_ + tid * 4] = a;
}

// ---------------- per-row LN stats (two-pass, numerically safe) ----------------
__global__ __launch_bounds__(256) void rowstat_kernel(
    const float* __restrict__ x, float* __restrict__ mean, float* __restrict__ rstd)
{
    __shared__ float red[256];
    int row = blockIdx.x, tid = threadIdx.x;
    float4 v = *(const float4*)&x[(size_t)row * D_ + tid * 4];
    float s = v.x + v.y + v.z + v.w;
    red[tid] = s; __syncthreads();
    #pragma unroll
    for (int o = 128; o > 0; o >>= 1) { if (tid < o) red[tid] += red[tid + o]; __syncthreads(); }
    float mu = red[0] * (1.0f / D_);
    __syncthreads();
    float dx = v.x - mu, dy = v.y - mu, dz = v.z - mu, dw = v.w - mu;
    red[tid] = dx*dx + dy*dy + dz*dz + dw*dw; __syncthreads();
    #pragma unroll
    for (int o = 128; o > 0; o >>= 1) { if (tid < o) red[tid] += red[tid + o]; __syncthreads(); }
    if (tid == 0) {
        mean[row] = mu;
        rstd[row] = rsqrtf(red[0] * (1.0f / D_) + EPS_);
    }
}

// ---------------- GEMM: C[M,Nc] = op(A)[M,K] * Bw[Nc,K]^T  (+ epilogue) ------
// LN: apply (a - mean[m]) * rstd[m] * g[k] + b[k] to A on load.
// EPI: 0 = none, 2 = bias + exact GELU, 3 = bias + residual add.
template<bool LN, int EPI>
__global__ __launch_bounds__(256) void gemm_nt(
    const float* __restrict__ A, const float* __restrict__ Bw,
    float* __restrict__ C, int M, int Nc, int K,
    const float* __restrict__ mean, const float* __restrict__ rstd,
    const float* __restrict__ lng, const float* __restrict__ lnb,
    const float* __restrict__ bias, const float* __restrict__ resid)
{
    __shared__ float As[16][128];
    __shared__ float Bs[16][128];
    __shared__ float musm[128], rssm[128];
    const int tid = threadIdx.x;
    const int bm0 = blockIdx.y * 128;
    const int bn0 = blockIdx.x * 128;
    const int tx = tid & 15, ty = tid >> 4;

    if (LN) {
        if (tid < 128) { musm[tid] = mean[bm0 + tid]; rssm[tid] = rstd[bm0 + tid]; }
    }
    __syncthreads();

    float acc[8][8];
    #pragma unroll
    for (int i = 0; i < 8; i++)
        #pragma unroll
        for (int j = 0; j < 8; j++) acc[i][j] = 0.0f;

    for (int k0 = 0; k0 < K; k0 += 16) {
        #pragma unroll
        for (int i = 0; i < 2; i++) {
            int f = tid + i * 256;
            int r = f >> 2, c4 = (f & 3) << 2;
            float4 v = *(const float4*)&A[(size_t)(bm0 + r) * K + k0 + c4];
            if (LN) {
                float mu = musm[r], rs = rssm[r];
                float4 gg = *(const float4*)&lng[k0 + c4];
                float4 bb = *(const float4*)&lnb[k0 + c4];
                v.x = (v.x - mu) * rs * gg.x + bb.x;
                v.y = (v.y - mu) * rs * gg.y + bb.y;
                v.z = (v.z - mu) * rs * gg.z + bb.z;
                v.w = (v.w - mu) * rs * gg.w + bb.w;
            }
            As[c4 + 0][r] = v.x; As[c4 + 1][r] = v.y;
            As[c4 + 2][r] = v.z; As[c4 + 3][r] = v.w;
            float4 w = *(const float4*)&Bw[(size_t)(bn0 + r) * K + k0 + c4];
            Bs[c4 + 0][r] = w.x; Bs[c4 + 1][r] = w.y;
            Bs[c4 + 2][r] = w.z; Bs[c4 + 3][r] = w.w;
        }
        __syncthreads();
        #pragma unroll
        for (int kk = 0; kk < 16; kk++) {
            float4 a0 = *(const float4*)&As[kk][ty * 8];
            float4 a1 = *(const float4*)&As[kk][ty * 8 + 4];
            float4 b0 = *(const float4*)&Bs[kk][tx * 8];
            float4 b1 = *(const float4*)&Bs[kk][tx * 8 + 4];
            float af[8] = {a0.x, a0.y, a0.z, a0.w, a1.x, a1.y, a1.z, a1.w};
            float bf[8] = {b0.x, b0.y, b0.z, b0.w, b1.x, b1.y, b1.z, b1.w};
            #pragma unroll
            for (int i = 0; i < 8; i++)
                #pragma unroll
                for (int j = 0; j < 8; j++)
                    acc[i][j] = fmaf(af[i], bf[j], acc[i][j]);
        }
        __syncthreads();
    }

    // epilogue (vectorized)
    #pragma unroll
    for (int i = 0; i < 8; i++) {
        int m = bm0 + ty * 8 + i;
        int n = bn0 + tx * 8;
        float o[8];
        #pragma unroll
        for (int j = 0; j < 8; j++) o[j] = acc[i][j];
        if (EPI >= 1) {
            float4 c0 = *(const float4*)&bias[n];
            float4 c1 = *(const float4*)&bias[n + 4];
            o[0]+=c0.x; o[1]+=c0.y; o[2]+=c0.z; o[3]+=c0.w;
            o[4]+=c1.x; o[5]+=c1.y; o[6]+=c1.z; o[7]+=c1.w;
        }
        if (EPI == 2) {
            #pragma unroll
            for (int j = 0; j < 8; j++)
                o[j] = 0.5f * o[j] * (1.0f + erff(o[j] * 0.70710678118654752f));
        }
        if (EPI == 3) {
            float4 r0 = *(const float4*)&resid[(size_t)m * Nc + n];
            float4 r1 = *(const float4*)&resid[(size_t)m * Nc + n + 4];
            o[0]+=r0.x; o[1]+=r0.y; o[2]+=r0.z; o[3]+=r0.w;
            o[4]+=r1.x; o[5]+=r1.y; o[6]+=r1.z; o[7]+=r1.w;
        }
        float4 w0 = make_float4(o[0], o[1], o[2], o[3]);
        float4 w1 = make_float4(o[4], o[5], o[6], o[7]);
        *(float4*)&C[(size_t)m * Nc + n] = w0;
        *(float4*)&C[(size_t)m * Nc + n + 4] = w1;
    }
}

// ---------------- kv-sum: kv[b,h,r,d] = sum_n relu(k.rf)[n,r] * v[n,d] -------
// phi_k computed on the fly; deterministic partials per 256-row chunk.
__global__ __launch_bounds__(256) void kvsum_kernel(
    const float* __restrict__ qkv, const float* __restrict__ rf_l,
    float* __restrict__ kvpart, float* __restrict__ kspart)
{
    __shared__ float rfsm[DH_ * R_];   // [d][r]
    __shared__ float ksm[4][64];
    __shared__ float vsm[4][64];
    __shared__ float phism[4][64];
    int tid = threadIdx.x;
    int bh = blockIdx.x;               // 0..31
    int b = bh >> 4, h = bh & 15;
    int chunk = blockIdx.y;            // 16 chunks of 256 rows

    const float* rfh = rf_l + h * (DH_ * R_);
    for (int i = tid; i < DH_ * R_; i += 256) rfsm[i] = rfh[i];
    __syncthreads();

    float acc[16];
    #pragma unroll
    for (int j = 0; j < 16; j++) acc[j] = 0.0f;
    int my_r  = tid >> 2;              // r = 0..63
    int my_d0 = (tid & 3) << 4;        // 16 d-cols
    int prow = tid >> 6, pr = tid & 63;
    float kslocal = 0.0f;
    int nbase = chunk * 256;

    for (int gidx = 0; gidx < 64; gidx++) {
        int n = nbase + gidx * 4 + prow;
        size_t base = ((size_t)(b * N_ + n)) * (3 * INNER_) + h * DH_;
        ksm[prow][pr] = qkv[base + INNER_ + pr];
        vsm[prow][pr] = qkv[base + 2 * INNER_ + pr];
        __syncthreads();
        float s = 0.0f;
        #pragma unroll
        for (int d = 0; d < 64; d++) s = fmaf(ksm[prow][d], rfsm[d * 64 + pr], s);
        s = fmaxf(s, 0.0f);
        phism[prow][pr] = s;
        kslocal += s;
        __syncthreads();
        #pragma unroll
        for (int rr = 0; rr < 4; rr++) {
            float p = phism[rr][my_r];
            #pragma unroll
            for (int j = 0; j < 16; j++)
                acc[j] = fmaf(p, vsm[rr][my_d0 + j], acc[j]);
        }
        __syncthreads();
    }

    float* kvp = kvpart + ((size_t)(bh * 16 + chunk)) * (R_ * DH_);
    #pragma unroll
    for (int j = 0; j < 16; j++) kvp[my_r * 64 + my_d0 + j] = acc[j];

    phism[prow][pr] = kslocal;   // reuse for ksum reduction
    __syncthreads();
    if (tid < 64) {
        float s = phism[0][tid] + phism[1][tid] + phism[2][tid] + phism[3][tid];
        kspart[(bh * 16 + chunk) * R_ + tid] = s;
    }
}

__global__ __launch_bounds__(256) void kvreduce_kernel(
    const float* __restrict__ kvpart, const float* __restrict__ kspart,
    float* __restrict__ kv, float* __restrict__ ks)
{
    int bh = blockIdx.x, tid = threadIdx.x;
    for (int i = tid; i < R_ * DH_; i += 256) {
        float s = 0.0f;
        #pragma unroll
        for (int c = 0; c < 16; c++)
            s += kvpart[((size_t)(bh * 16 + c)) * (R_ * DH_) + i];
        kv[(size_t)bh * (R_ * DH_) + i] = s;
    }
    if (tid < 64) {
        float s = 0.0f;
        #pragma unroll
        for (int c = 0; c < 16; c++) s += kspart[(bh * 16 + c) * R_ + tid];
        ks[bh * R_ + tid] = s;
    }
}

// ---------------- attention out: out = (phi_q @ kv) / (phi_q . ksum + stab) --
__global__ __launch_bounds__(256) void attnout_kernel(
    const float* __restrict__ qkv, const float* __restrict__ rf_l,
    const float* __restrict__ kv, const float* __restrict__ ksum,
    float* __restrict__ out)
{
    __shared__ float rfsm[DH_ * R_];   // [d][r]
    __shared__ float kvsm[R_ * DH_];   // [r][d]
    __shared__ float kssm[R_];
    __shared__ float qsm[4][64];
    __shared__ float phism[4][64];
    int tid = threadIdx.x;
    int bh = blockIdx.x;
    int b = bh >> 4, h = bh & 15;
    int tile = blockIdx.y;             // 32 tiles of 128 rows

    const float* rfh = rf_l + h * (DH_ * R_);
    for (int i = tid; i < DH_ * R_; i += 256) {
        rfsm[i] = rfh[i];
        kvsm[i] = kv[(size_t)bh * (R_ * DH_) + i];
    }
    if (tid < 64) kssm[tid] = ksum[bh * R_ + tid];
    __syncthreads();

    int prow = tid >> 6, pr = tid & 63;
    int nbase = tile * 128;
    for (int gidx = 0; gidx < 32; gidx++) {
        int n = nbase + gidx * 4 + prow;
        size_t base = ((size_t)(b * N_ + n)) * (3 * INNER_) + h * DH_;
        qsm[prow][pr] = qkv[base + pr];
        __syncthreads();
        float s = 0.0f;
        #pragma unroll
        for (int d = 0; d < 64; d++) s = fmaf(qsm[prow][d], rfsm[d * 64 + pr], s);
        s = fmaxf(s, 0.0f);
        phism[prow][pr] = s;
        __syncthreads();
        float accv = 0.0f, nz = 0.0f;
        #pragma unroll
        for (int r = 0; r < 64; r++) {
            float p = phism[prow][r];
            accv = fmaf(p, kvsm[r * 64 + pr], accv);
            nz   = fmaf(p, kssm[r], nz);
        }
        out[((size_t)(b * N_ + n)) * INNER_ + h * DH_ + pr] = accv / (nz + STAB_);
        __syncthreads();
    }
}

// ---------------- host driver ----------------
extern "C" void kernel_launch(void* const* d_in, const int* in_sizes, int n_in,
                              void* d_out, int out_size)
{
    const int*   tokens  = (const int*)  d_in[0];
    const float* tok_emb = (const float*)d_in[1];
    const float* pos_emb = (const float*)d_in[2];
    const float* Wqkv    = (const float*)d_in[3];
    const float* Wout    = (const float*)d_in[4];
    const float* bout    = (const float*)d_in[5];
    const float* ln1g    = (const float*)d_in[6];
    const float* ln1b    = (const float*)d_in[7];
    const float* ln2g    = (const float*)d_in[8];
    const float* ln2b    = (const float*)d_in[9];
    const float* W1      = (const float*)d_in[10];
    const float* b1      = (const float*)d_in[11];
    const float* W2      = (const float*)d_in[12];
    const float* b2      = (const float*)d_in[13];
    const float* rf      = (const float*)d_in[14];
    float* x = (float*)d_out;

    float *qkv, *ff1, *attnout, *kvpart, *kspart, *kv, *ksum, *mean, *rstd;
    cudaGetSymbolAddress((void**)&qkv,     g_qkv);
    cudaGetSymbolAddress((void**)&ff1,     g_ff1);
    cudaGetSymbolAddress((void**)&attnout, g_attnout);
    cudaGetSymbolAddress((void**)&kvpart,  g_kvpart);
    cudaGetSymbolAddress((void**)&kspart,  g_kspart);
    cudaGetSymbolAddress((void**)&kv,      g_kv);
    cudaGetSymbolAddress((void**)&ksum,    g_ksum);
    cudaGetSymbolAddress((void**)&mean,    g_mean);
    cudaGetSymbolAddress((void**)&rstd,    g_rstd);

    embed_kernel<<<M_, 256>>>(tokens, tok_emb, pos_emb, x);

    for (int l = 0; l < L_; l++) {
        const float* Wqkv_l = Wqkv + (size_t)l * 3 * INNER_ * D_;
        const float* Wout_l = Wout + (size_t)l * D_ * INNER_;
        const float* bout_l = bout + (size_t)l * D_;
        const float* ln1g_l = ln1g + (size_t)l * D_;
        const float* ln1b_l = ln1b + (size_t)l * D_;
        const float* ln2g_l = ln2g + (size_t)l * D_;
        const float* ln2b_l = ln2b + (size_t)l * D_;
        const float* W1_l   = W1   + (size_t)l * FF_ * D_;
        const float* b1_l   = b1   + (size_t)l * FF_;
        const float* W2_l   = W2   + (size_t)l * D_ * FF_;
        const float* b2_l   = b2   + (size_t)l * D_;
        const float* rf_l   = rf   + (size_t)l * H_ * DH_ * R_;

        // --- attention block ---
        rowstat_kernel<<<M_, 256>>>(x, mean, rstd);
        gemm_nt<true, 0><<<dim3(3 * INNER_ / 128, M_ / 128), 256>>>(
            x, Wqkv_l, qkv, M_, 3 * INNER_, D_,
            mean, rstd, ln1g_l, ln1b_l, nullptr, nullptr);
        kvsum_kernel<<<dim3(B_ * H_, 16), 256>>>(qkv, rf_l, kvpart, kspart);
        kvreduce_kernel<<<B_ * H_, 256>>>(kvpart, kspart, kv, ksum);
        attnout_kernel<<<dim3(B_ * H_, N_ / 128), 256>>>(qkv, rf_l, kv, ksum, attnout);
        gemm_nt<false, 3><<<dim3(D_ / 128, M_ / 128), 256>>>(
            attnout, Wout_l, x, M_, D_, INNER_,
            nullptr, nullptr, nullptr, nullptr, bout_l, x);

        // --- FFN block ---
        rowstat_kernel<<<M_, 256>>>(x, mean, rstd);
        gemm_nt<true, 2><<<dim3(FF_ / 128, M_ / 128), 256>>>(
            x, W1_l, ff1, M_, FF_, D_,
            mean, rstd, ln2g_l, ln2b_l, b1_l, nullptr);
        gemm_nt<false, 3><<<dim3(D_ / 128, M_ / 128), 256>>>(
            ff1, W2_l, x, M_, D_, FF_,
            nullptr, nullptr, nullptr, nullptr, b2_l, x);
    }
}

// round 7
// speedup vs baseline: 2.7525x; 2.7525x over previous
#include <cuda_runtime.h>
#include <cuda_bf16.h>
#include <math.h>
#include <stdint.h>

// ---------------- problem constants ----------------
#define B_   2
#define N_   4096
#define D_   1024
#define H_   16
#define DH_  64
#define R_   64
#define L_   6
#define FF_  4096
#define INNER_ 1024
#define M_   (B_*N_)        // 8192 rows
#define EPS_ 1e-5f
#define STAB_ 1e-6f

// ---------------- scratch (static device globals; allowed) ----------------
__device__ __align__(16) float g_qkv[M_ * 3 * INNER_];      // 96 MB
__device__ __align__(16) float g_ff1[M_ * FF_];             // 128 MB
__device__ __align__(16) float g_attnout[M_ * INNER_];      // 32 MB
__device__ __align__(16) float g_ln[M_ * D_];               // 32 MB
__device__ __align__(16) float g_kvpart[B_*H_*16*R_*DH_];   // 8 MB
__device__ __align__(16) float g_kspart[B_*H_*16*R_];
__device__ __align__(16) float g_kv[B_*H_*R_*DH_];
__device__ __align__(16) float g_ksum[B_*H_*R_];

// ---------------- embedding ----------------
__global__ __launch_bounds__(256) void embed_kernel(
    const int* __restrict__ tokens, const float* __restrict__ te,
    const float* __restrict__ pe, float* __restrict__ x)
{
    int row = blockIdx.x;
    int tid = threadIdx.x;
    int n = row & (N_ - 1);
    int tok = tokens[row];
    float4 a = *(const float4*)&te[(size_t)tok * D_ + tid * 4];
    float4 p = *(const float4*)&pe[(size_t)n * D_ + tid * 4];
    a.x += p.x; a.y += p.y; a.z += p.z; a.w += p.w;
    *(float4*)&x[(size_t)row * D_ + tid * 4] = a;
}

// ---------------- fused LayerNorm (stats + apply) ----------------
__global__ __launch_bounds__(256) void ln_kernel(
    const float* __restrict__ x, const float* __restrict__ lng,
    const float* __restrict__ lnb, float* __restrict__ h)
{
    __shared__ float red[256];
    int row = blockIdx.x, tid = threadIdx.x;
    float4 v = *(const float4*)&x[(size_t)row * D_ + tid * 4];
    red[tid] = v.x + v.y + v.z + v.w; __syncthreads();
    #pragma unroll
    for (int o = 128; o > 0; o >>= 1) { if (tid < o) red[tid] += red[tid + o]; __syncthreads(); }
    float mu = red[0] * (1.0f / D_);
    __syncthreads();
    float dx = v.x - mu, dy = v.y - mu, dz = v.z - mu, dw = v.w - mu;
    red[tid] = dx*dx + dy*dy + dz*dz + dw*dw; __syncthreads();
    #pragma unroll
    for (int o = 128; o > 0; o >>= 1) { if (tid < o) red[tid] += red[tid + o]; __syncthreads(); }
    float rs = rsqrtf(red[0] * (1.0f / D_) + EPS_);
    float4 gg = *(const float4*)&lng[tid * 4];
    float4 bb = *(const float4*)&lnb[tid * 4];
    float4 o4;
    o4.x = dx * rs * gg.x + bb.x;
    o4.y = dy * rs * gg.y + bb.y;
    o4.z = dz * rs * gg.z + bb.z;
    o4.w = dw * rs * gg.w + bb.w;
    *(float4*)&h[(size_t)row * D_ + tid * 4] = o4;
}

// ---------------- TF32 tensor-core GEMM ----------------
// C[M,Nc] = A[M,K] @ Bw[Nc,K]^T  (+ epilogue)
// EPI: 0 = none, 2 = bias + exact GELU, 3 = bias + residual add.
#define PAD_ 20   // 16 + 4: fragment LDS provably conflict-free

__device__ __forceinline__ void cp_async16(void* smem, const void* gmem) {
    unsigned s = (unsigned)__cvta_generic_to_shared(smem);
    asm volatile("cp.async.cg.shared.global [%0], [%1], 16;\n" :: "r"(s), "l"(gmem));
}
__device__ __forceinline__ uint32_t f2tf32(float x) {
    uint32_t u;
    asm("cvt.rna.tf32.f32 %0, %1;" : "=r"(u) : "f"(x));
    return u;
}

template<int EPI>
__global__ __launch_bounds__(256) void gemm_tc(
    const float* __restrict__ A, const float* __restrict__ Bw,
    float* __restrict__ C, int M, int Nc, int K,
    const float* __restrict__ bias, const float* __restrict__ resid)
{
    __shared__ __align__(16) float As[2][128 * PAD_];
    __shared__ __align__(16) float Bs[2][128 * PAD_];

    const int tid  = threadIdx.x;
    const int bm0  = blockIdx.y * 128;
    const int bn0  = blockIdx.x * 128;
    const int warp = tid >> 5;
    const int lane = tid & 31;
    const int wm   = warp >> 2;     // 0..1 -> 64-row slab
    const int wn   = warp & 3;      // 0..3 -> 32-col slab
    const int grp  = lane >> 2;     // 0..7
    const int qid  = lane & 3;      // 0..3

    float c[4][4][4];
    #pragma unroll
    for (int mi = 0; mi < 4; mi++)
        #pragma unroll
        for (int ni = 0; ni < 4; ni++)
            #pragma unroll
            for (int j = 0; j < 4; j++) c[mi][ni][j] = 0.0f;

    const int nIter = K >> 4;

    // stage loader: 4 x 16B cp.async per thread
    auto load_stage = [&](int it, int buf) {
        int k0 = it << 4;
        #pragma unroll
        for (int i = 0; i < 2; i++) {
            int f  = tid + i * 256;        // 0..511
            int m  = f >> 2;
            int c4 = (f & 3) << 2;
            cp_async16(&As[buf][m * PAD_ + c4], &A [(size_t)(bm0 + m) * K + k0 + c4]);
            cp_async16(&Bs[buf][m * PAD_ + c4], &Bw[(size_t)(bn0 + m) * K + k0 + c4]);
        }
        asm volatile("cp.async.commit_group;\n" ::: "memory");
    };

    load_stage(0, 0);

    for (int it = 0; it < nIter; it++) {
        int buf = it & 1;
        if (it + 1 < nIter) {
            load_stage(it + 1, buf ^ 1);
            asm volatile("cp.async.wait_group 1;\n" ::: "memory");
        } else {
            asm volatile("cp.async.wait_group 0;\n" ::: "memory");
        }
        __syncthreads();

        const float* As_ = As[buf];
        const float* Bs_ = Bs[buf];

        #pragma unroll
        for (int ks = 0; ks < 16; ks += 8) {
            uint32_t af[4][4], bf[4][2];
            #pragma unroll
            for (int mi = 0; mi < 4; mi++) {
                int m = wm * 64 + mi * 16 + grp;
                af[mi][0] = f2tf32(As_[ m      * PAD_ + ks + qid    ]);
                af[mi][1] = f2tf32(As_[(m + 8) * PAD_ + ks + qid    ]);
                af[mi][2] = f2tf32(As_[ m      * PAD_ + ks + qid + 4]);
                af[mi][3] = f2tf32(As_[(m + 8) * PAD_ + ks + qid + 4]);
            }
            #pragma unroll
            for (int ni = 0; ni < 4; ni++) {
                int n = wn * 32 + ni * 8 + grp;
                bf[ni][0] = f2tf32(Bs_[n * PAD_ + ks + qid    ]);
                bf[ni][1] = f2tf32(Bs_[n * PAD_ + ks + qid + 4]);
            }
            #pragma unroll
            for (int mi = 0; mi < 4; mi++)
                #pragma unroll
                for (int ni = 0; ni < 4; ni++) {
                    asm volatile(
                        "mma.sync.aligned.m16n8k8.row.col.f32.tf32.tf32.f32 "
                        "{%0,%1,%2,%3}, {%4,%5,%6,%7}, {%8,%9}, {%0,%1,%2,%3};\n"
                        : "+f"(c[mi][ni][0]), "+f"(c[mi][ni][1]),
                          "+f"(c[mi][ni][2]), "+f"(c[mi][ni][3])
                        : "r"(af[mi][0]), "r"(af[mi][1]), "r"(af[mi][2]), "r"(af[mi][3]),
                          "r"(bf[ni][0]), "r"(bf[ni][1]));
                }
        }
        __syncthreads();
    }

    // ---- epilogue ----
    #pragma unroll
    for (int mi = 0; mi < 4; mi++) {
        int row0 = bm0 + wm * 64 + mi * 16 + grp;
        int row1 = row0 + 8;
        #pragma unroll
        for (int ni = 0; ni < 4; ni++) {
            int col = bn0 + wn * 32 + ni * 8 + qid * 2;
            float o0 = c[mi][ni][0], o1 = c[mi][ni][1];
            float o2 = c[mi][ni][2], o3 = c[mi][ni][3];
            if (EPI >= 1) {
                float b0 = bias[col], b1 = bias[col + 1];
                o0 += b0; o1 += b1; o2 += b0; o3 += b1;
            }
            if (EPI == 2) {
                o0 = 0.5f * o0 * (1.0f + erff(o0 * 0.70710678118654752f));
                o1 = 0.5f * o1 * (1.0f + erff(o1 * 0.70710678118654752f));
                o2 = 0.5f * o2 * (1.0f + erff(o2 * 0.70710678118654752f));
                o3 = 0.5f * o3 * (1.0f + erff(o3 * 0.70710678118654752f));
            }
            if (EPI == 3) {
                float2 r0 = *(const float2*)&resid[(size_t)row0 * Nc + col];
                float2 r1 = *(const float2*)&resid[(size_t)row1 * Nc + col];
                o0 += r0.x; o1 += r0.y; o2 += r1.x; o3 += r1.y;
            }
            *(float2*)&C[(size_t)row0 * Nc + col] = make_float2(o0, o1);
            *(float2*)&C[(size_t)row1 * Nc + col] = make_float2(o2, o3);
        }
    }
}

// ---------------- kv-sum: kv[b,h,r,d] = sum_n relu(k.rf)[n,r] * v[n,d] -------
__global__ __launch_bounds__(256) void kvsum_kernel(
    const float* __restrict__ qkv, const float* __restrict__ rf_l,
    float* __restrict__ kvpart, float* __restrict__ kspart)
{
    __shared__ float rfsm[DH_ * R_];
    __shared__ float ksm[4][64];
    __shared__ float vsm[4][64];
    __shared__ float phism[4][64];
    int tid = threadIdx.x;
    int bh = blockIdx.x;
    int b = bh >> 4, h = bh & 15;
    int chunk = blockIdx.y;

    const float* rfh = rf_l + h * (DH_ * R_);
    for (int i = tid; i < DH_ * R_; i += 256) rfsm[i] = rfh[i];
    __syncthreads();

    float acc[16];
    #pragma unroll
    for (int j = 0; j < 16; j++) acc[j] = 0.0f;
    int my_r  = tid >> 2;
    int my_d0 = (tid & 3) << 4;
    int prow = tid >> 6, pr = tid & 63;
    float kslocal = 0.0f;
    int nbase = chunk * 256;

    for (int gidx = 0; gidx < 64; gidx++) {
        int n = nbase + gidx * 4 + prow;
        size_t base = ((size_t)(b * N_ + n)) * (3 * INNER_) + h * DH_;
        ksm[prow][pr] = qkv[base + INNER_ + pr];
        vsm[prow][pr] = qkv[base + 2 * INNER_ + pr];
        __syncthreads();
        float s = 0.0f;
        #pragma unroll
        for (int d = 0; d < 64; d++) s = fmaf(ksm[prow][d], rfsm[d * 64 + pr], s);
        s = fmaxf(s, 0.0f);
        phism[prow][pr] = s;
        kslocal += s;
        __syncthreads();
        #pragma unroll
        for (int rr = 0; rr < 4; rr++) {
            float p = phism[rr][my_r];
            #pragma unroll
            for (int j = 0; j < 16; j++)
                acc[j] = fmaf(p, vsm[rr][my_d0 + j], acc[j]);
        }
        __syncthreads();
    }

    float* kvp = kvpart + ((size_t)(bh * 16 + chunk)) * (R_ * DH_);
    #pragma unroll
    for (int j = 0; j < 16; j++) kvp[my_r * 64 + my_d0 + j] = acc[j];

    phism[prow][pr] = kslocal;
    __syncthreads();
    if (tid < 64) {
        float s = phism[0][tid] + phism[1][tid] + phism[2][tid] + phism[3][tid];
        kspart[(bh * 16 + chunk) * R_ + tid] = s;
    }
}

__global__ __launch_bounds__(256) void kvreduce_kernel(
    const float* __restrict__ kvpart, const float* __restrict__ kspart,
    float* __restrict__ kv, float* __restrict__ ks)
{
    int bh = blockIdx.x, tid = threadIdx.x;
    for (int i = tid; i < R_ * DH_; i += 256) {
        float s = 0.0f;
        #pragma unroll
        for (int c = 0; c < 16; c++)
            s += kvpart[((size_t)(bh * 16 + c)) * (R_ * DH_) + i];
        kv[(size_t)bh * (R_ * DH_) + i] = s;
    }
    if (tid < 64) {
        float s = 0.0f;
        #pragma unroll
        for (int c = 0; c < 16; c++) s += kspart[(bh * 16 + c) * R_ + tid];
        ks[bh * R_ + tid] = s;
    }
}

// ---------------- attention out ----------------
__global__ __launch_bounds__(256) void attnout_kernel(
    const float* __restrict__ qkv, const float* __restrict__ rf_l,
    const float* __restrict__ kv, const float* __restrict__ ksum,
    float* __restrict__ out)
{
    __shared__ float rfsm[DH_ * R_];
    __shared__ float kvsm[R_ * DH_];
    __shared__ float kssm[R_];
    __shared__ float qsm[4][64];
    __shared__ float phism[4][64];
    int tid = threadIdx.x;
    int bh = blockIdx.x;
    int b = bh >> 4, h = bh & 15;
    int tile = blockIdx.y;

    const float* rfh = rf_l + h * (DH_ * R_);
    for (int i = tid; i < DH_ * R_; i += 256) {
        rfsm[i] = rfh[i];
        kvsm[i] = kv[(size_t)bh * (R_ * DH_) + i];
    }
    if (tid < 64) kssm[tid] = ksum[bh * R_ + tid];
    __syncthreads();

    int prow = tid >> 6, pr = tid & 63;
    int nbase = tile * 128;
    for (int gidx = 0; gidx < 32; gidx++) {
        int n = nbase + gidx * 4 + prow;
        size_t base = ((size_t)(b * N_ + n)) * (3 * INNER_) + h * DH_;
        qsm[prow][pr] = qkv[base + pr];
        __syncthreads();
        float s = 0.0f;
        #pragma unroll
        for (int d = 0; d < 64; d++) s = fmaf(qsm[prow][d], rfsm[d * 64 + pr], s);
        s = fmaxf(s, 0.0f);
        phism[prow][pr] = s;
        __syncthreads();
        float accv = 0.0f, nz = 0.0f;
        #pragma unroll
        for (int r = 0; r < 64; r++) {
            float p = phism[prow][r];
            accv = fmaf(p, kvsm[r * 64 + pr], accv);
            nz   = fmaf(p, kssm[r], nz);
        }
        out[((size_t)(b * N_ + n)) * INNER_ + h * DH_ + pr] = accv / (nz + STAB_);
        __syncthreads();
    }
}

// ---------------- host driver ----------------
extern "C" void kernel_launch(void* const* d_in, const int* in_sizes, int n_in,
                              void* d_out, int out_size)
{
    const int*   tokens  = (const int*)  d_in[0];
    const float* tok_emb = (const float*)d_in[1];
    const float* pos_emb = (const float*)d_in[2];
    const float* Wqkv    = (const float*)d_in[3];
    const float* Wout    = (const float*)d_in[4];
    const float* bout    = (const float*)d_in[5];
    const float* ln1g    = (const float*)d_in[6];
    const float* ln1b    = (const float*)d_in[7];
    const float* ln2g    = (const float*)d_in[8];
    const float* ln2b    = (const float*)d_in[9];
    const float* W1      = (const float*)d_in[10];
    const float* b1      = (const float*)d_in[11];
    const float* W2      = (const float*)d_in[12];
    const float* b2      = (const float*)d_in[13];
    const float* rf      = (const float*)d_in[14];
    float* x = (float*)d_out;

    float *qkv, *ff1, *attnout, *ln, *kvpart, *kspart, *kv, *ksum;
    cudaGetSymbolAddress((void**)&qkv,     g_qkv);
    cudaGetSymbolAddress((void**)&ff1,     g_ff1);
    cudaGetSymbolAddress((void**)&attnout, g_attnout);
    cudaGetSymbolAddress((void**)&ln,      g_ln);
    cudaGetSymbolAddress((void**)&kvpart,  g_kvpart);
    cudaGetSymbolAddress((void**)&kspart,  g_kspart);
    cudaGetSymbolAddress((void**)&kv,      g_kv);
    cudaGetSymbolAddress((void**)&ksum,    g_ksum);

    embed_kernel<<<M_, 256>>>(tokens, tok_emb, pos_emb, x);

    for (int l = 0; l < L_; l++) {
        const float* Wqkv_l = Wqkv + (size_t)l * 3 * INNER_ * D_;
        const float* Wout_l = Wout + (size_t)l * D_ * INNER_;
        const float* bout_l = bout + (size_t)l * D_;
        const float* ln1g_l = ln1g + (size_t)l * D_;
        const float* ln1b_l = ln1b + (size_t)l * D_;
        const float* ln2g_l = ln2g + (size_t)l * D_;
        const float* ln2b_l = ln2b + (size_t)l * D_;
        const float* W1_l   = W1   + (size_t)l * FF_ * D_;
        const float* b1_l   = b1   + (size_t)l * FF_;
        const float* W2_l   = W2   + (size_t)l * D_ * FF_;
        const float* b2_l   = b2   + (size_t)l * D_;
        const float* rf_l   = rf   + (size_t)l * H_ * DH_ * R_;

        // --- attention block ---
        ln_kernel<<<M_, 256>>>(x, ln1g_l, ln1b_l, ln);
        gemm_tc<0><<<dim3(3 * INNER_ / 128, M_ / 128), 256>>>(
            ln, Wqkv_l, qkv, M_, 3 * INNER_, D_, nullptr, nullptr);
        kvsum_kernel<<<dim3(B_ * H_, 16), 256>>>(qkv, rf_l, kvpart, kspart);
        kvreduce_kernel<<<B_ * H_, 256>>>(kvpart, kspart, kv, ksum);
        attnout_kernel<<<dim3(B_ * H_, N_ / 128), 256>>>(qkv, rf_l, kv, ksum, attnout);
        gemm_tc<3><<<dim3(D_ / 128, M_ / 128), 256>>>(
            attnout, Wout_l, x, M_, D_, INNER_, bout_l, x);

        // --- FFN block ---
        ln_kernel<<<M_, 256>>>(x, ln2g_l, ln2b_l, ln);
        gemm_tc<2><<<dim3(FF_ / 128, M_ / 128), 256>>>(
            ln, W1_l, ff1, M_, FF_, D_, b1_l, nullptr);
        gemm_tc<3><<<dim3(D_ / 128, M_ / 128), 256>>>(
            ff1, W2_l, x, M_, D_, FF_, b2_l, x);
    }
}

// round 8
// speedup vs baseline: 3.1095x; 1.1297x over previous
#include <cuda_runtime.h>
#include <cuda_bf16.h>
#include <math.h>
#include <stdint.h>

// ---------------- problem constants ----------------
#define B_   2
#define N_   4096
#define D_   1024
#define H_   16
#define DH_  64
#define R_   64
#define L_   6
#define FF_  4096
#define INNER_ 1024
#define M_   (B_*N_)        // 8192 rows
#define EPS_ 1e-5f
#define STAB_ 1e-6f

// ---------------- scratch (static device globals; allowed) ----------------
__device__ __align__(16) float g_qkv[M_ * 3 * INNER_];      // 96 MB
__device__ __align__(16) float g_ff1[M_ * FF_];             // 128 MB (tf32, k-permuted)
__device__ __align__(16) float g_attnout[M_ * INNER_];      // 32 MB (tf32, k-permuted)
__device__ __align__(16) float g_ln[M_ * D_];               // 32 MB (tf32, k-permuted)
__device__ __align__(16) float g_kvpart[B_*H_*16*R_*DH_];
__device__ __align__(16) float g_kspart[B_*H_*16*R_];
__device__ __align__(16) float g_kv[B_*H_*R_*DH_];
__device__ __align__(16) float g_ksum[B_*H_*R_];
// tf32-rounded, k-permuted weight copies
__device__ __align__(16) float g_Wqkvp[L_*3*INNER_*D_];     // 75.5 MB
__device__ __align__(16) float g_Woutp[L_*D_*INNER_];       // 25 MB
__device__ __align__(16) float g_W1p  [L_*FF_*D_];          // 100 MB
__device__ __align__(16) float g_W2p  [L_*D_*FF_];          // 100 MB

// ---------------- helpers ----------------
__device__ __forceinline__ uint32_t f2tf32(float x) {
    uint32_t u;
    asm("cvt.rna.tf32.f32 %0, %1;" : "=r"(u) : "f"(x));
    return u;
}
__device__ __forceinline__ float tf32r(float x) { return __uint_as_float(f2tf32(x)); }
__device__ __forceinline__ void cp_async16(void* smem, const void* gmem) {
    unsigned s = (unsigned)__cvta_generic_to_shared(smem);
    asm volatile("cp.async.cg.shared.global [%0], [%1], 16;\n" :: "r"(s), "l"(gmem));
}
// k-permutation within 8-groups: pairs (k, k+4) become adjacent
__device__ __forceinline__ int kperm(int k) {
    return (k & ~7) | ((k & 3) << 1) | ((k >> 2) & 1);
}

// ---------------- weight convert: tf32-round + k-permute (8 elems/thread) ---
__global__ __launch_bounds__(256) void wconv_kernel(
    const float* __restrict__ in, float* __restrict__ out, int n8)
{
    int i = blockIdx.x * 256 + threadIdx.x;
    if (i >= n8) return;
    size_t base = (size_t)i * 8;
    float4 v0 = *(const float4*)&in[base];
    float4 v1 = *(const float4*)&in[base + 4];
    // positions 0..7 hold logical k {0,4,1,5,2,6,3,7}
    float4 o0 = make_float4(tf32r(v0.x), tf32r(v1.x), tf32r(v0.y), tf32r(v1.y));
    float4 o1 = make_float4(tf32r(v0.z), tf32r(v1.z), tf32r(v0.w), tf32r(v1.w));
    *(float4*)&out[base]     = o0;
    *(float4*)&out[base + 4] = o1;
}

// ---------------- embedding ----------------
__global__ __launch_bounds__(256) void embed_kernel(
    const int* __restrict__ tokens, const float* __restrict__ te,
    const float* __restrict__ pe, float* __restrict__ x)
{
    int row = blockIdx.x;
    int tid = threadIdx.x;
    int n = row & (N_ - 1);
    int tok = tokens[row];
    float4 a = *(const float4*)&te[(size_t)tok * D_ + tid * 4];
    float4 p = *(const float4*)&pe[(size_t)n * D_ + tid * 4];
    a.x += p.x; a.y += p.y; a.z += p.z; a.w += p.w;
    *(float4*)&x[(size_t)row * D_ + tid * 4] = a;
}

// ---------------- fused LayerNorm: stats + apply + tf32-round + k-permute ---
__global__ __launch_bounds__(256) void ln_kernel(
    const float* __restrict__ x, const float* __restrict__ lng,
    const float* __restrict__ lnb, float* __restrict__ h)
{
    __shared__ float red[256];
    int row = blockIdx.x, tid = threadIdx.x;
    float4 v = *(const float4*)&x[(size_t)row * D_ + tid * 4];
    red[tid] = v.x + v.y + v.z + v.w; __syncthreads();
    #pragma unroll
    for (int o = 128; o > 0; o >>= 1) { if (tid < o) red[tid] += red[tid + o]; __syncthreads(); }
    float mu = red[0] * (1.0f / D_);
    __syncthreads();
    float dx = v.x - mu, dy = v.y - mu, dz = v.z - mu, dw = v.w - mu;
    red[tid] = dx*dx + dy*dy + dz*dz + dw*dw; __syncthreads();
    #pragma unroll
    for (int o = 128; o > 0; o >>= 1) { if (tid < o) red[tid] += red[tid + o]; __syncthreads(); }
    float rs = rsqrtf(red[0] * (1.0f / D_) + EPS_);
    float4 gg = *(const float4*)&lng[tid * 4];
    float4 bb = *(const float4*)&lnb[tid * 4];
    float o0 = dx * rs * gg.x + bb.x;
    float o1 = dy * rs * gg.y + bb.y;
    float o2 = dz * rs * gg.z + bb.z;
    float o3 = dw * rs * gg.w + bb.w;
    float* hr = h + (size_t)row * D_;
    int c0 = tid * 4;
    hr[kperm(c0 + 0)] = tf32r(o0);
    hr[kperm(c0 + 1)] = tf32r(o1);
    hr[kperm(c0 + 2)] = tf32r(o2);
    hr[kperm(c0 + 3)] = tf32r(o3);
}

// ---------------- TF32 tensor-core GEMM (operands pre-rounded + permuted) ---
// C[M,Nc] = A[M,K] @ Bw[Nc,K]^T  (+ epilogue)
// EPI: 0 = none, 2 = bias + GELU, 3 = bias + residual.
// PERM: epilogue output is tf32-rounded & k-permuted (for next GEMM's A).
#define PADG 24

template<int EPI, bool PERM>
__global__ __launch_bounds__(256) void gemm_tc(
    const float* __restrict__ A, const float* __restrict__ Bw,
    float* __restrict__ C, int M, int Nc, int K,
    const float* __restrict__ bias, const float* __restrict__ resid)
{
    __shared__ __align__(16) float As[2][128 * PADG];
    __shared__ __align__(16) float Bs[2][128 * PADG];

    const int tid  = threadIdx.x;
    const int bm0  = blockIdx.y * 128;
    const int bn0  = blockIdx.x * 128;
    const int warp = tid >> 5;
    const int lane = tid & 31;
    const int wm   = warp >> 2;     // 0..1 -> 64-row slab
    const int wn   = warp & 3;      // 0..3 -> 32-col slab
    const int grp  = lane >> 2;     // 0..7
    const int qid  = lane & 3;      // 0..3

    float c[4][4][4];
    #pragma unroll
    for (int mi = 0; mi < 4; mi++)
        #pragma unroll
        for (int ni = 0; ni < 4; ni++)
            #pragma unroll
            for (int j = 0; j < 4; j++) c[mi][ni][j] = 0.0f;

    const int nIter = K >> 4;

    auto load_stage = [&](int it, int buf) {
        int k0 = it << 4;
        #pragma unroll
        for (int i = 0; i < 2; i++) {
            int f  = tid + i * 256;
            int m  = f >> 2;
            int c4 = (f & 3) << 2;
            cp_async16(&As[buf][m * PADG + c4], &A [(size_t)(bm0 + m) * K + k0 + c4]);
            cp_async16(&Bs[buf][m * PADG + c4], &Bw[(size_t)(bn0 + m) * K + k0 + c4]);
        }
        asm volatile("cp.async.commit_group;\n" ::: "memory");
    };

    load_stage(0, 0);

    for (int it = 0; it < nIter; it++) {
        int buf = it & 1;
        if (it + 1 < nIter) {
            load_stage(it + 1, buf ^ 1);
            asm volatile("cp.async.wait_group 1;\n" ::: "memory");
        } else {
            asm volatile("cp.async.wait_group 0;\n" ::: "memory");
        }
        __syncthreads();

        const float* As_ = As[buf];
        const float* Bs_ = Bs[buf];

        #pragma unroll
        for (int ks = 0; ks < 16; ks += 8) {
            // paired fragment loads (LDS.64): pos ks+2q holds k=q, pos ks+2q+1 holds k=q+4
            uint32_t af[4][4], bf[4][2];
            #pragma unroll
            for (int mi = 0; mi < 4; mi++) {
                int m = wm * 64 + mi * 16 + grp;
                float2 pA0 = *(const float2*)&As_[ m      * PADG + ks + 2 * qid];
                float2 pA1 = *(const float2*)&As_[(m + 8) * PADG + ks + 2 * qid];
                af[mi][0] = __float_as_uint(pA0.x);
                af[mi][1] = __float_as_uint(pA1.x);
                af[mi][2] = __float_as_uint(pA0.y);
                af[mi][3] = __float_as_uint(pA1.y);
            }
            #pragma unroll
            for (int ni = 0; ni < 4; ni++) {
                int n = wn * 32 + ni * 8 + grp;
                float2 pB = *(const float2*)&Bs_[n * PADG + ks + 2 * qid];
                bf[ni][0] = __float_as_uint(pB.x);
                bf[ni][1] = __float_as_uint(pB.y);
            }
            #pragma unroll
            for (int mi = 0; mi < 4; mi++)
                #pragma unroll
                for (int ni = 0; ni < 4; ni++) {
                    asm volatile(
                        "mma.sync.aligned.m16n8k8.row.col.f32.tf32.tf32.f32 "
                        "{%0,%1,%2,%3}, {%4,%5,%6,%7}, {%8,%9}, {%0,%1,%2,%3};\n"
                        : "+f"(c[mi][ni][0]), "+f"(c[mi][ni][1]),
                          "+f"(c[mi][ni][2]), "+f"(c[mi][ni][3])
                        : "r"(af[mi][0]), "r"(af[mi][1]), "r"(af[mi][2]), "r"(af[mi][3]),
                          "r"(bf[ni][0]), "r"(bf[ni][1]));
                }
        }
        __syncthreads();
    }

    // ---- epilogue ----
    #pragma unroll
    for (int mi = 0; mi < 4; mi++) {
        int row0 = bm0 + wm * 64 + mi * 16 + grp;
        int row1 = row0 + 8;
        #pragma unroll
        for (int ni = 0; ni < 4; ni++) {
            int colbase = bn0 + wn * 32 + ni * 8;
            int j0 = qid * 2, j1 = j0 + 1;
            float o0 = c[mi][ni][0], o1 = c[mi][ni][1];
            float o2 = c[mi][ni][2], o3 = c[mi][ni][3];
            if (EPI >= 1) {
                float b0 = bias[colbase + j0], b1 = bias[colbase + j1];
                o0 += b0; o1 += b1; o2 += b0; o3 += b1;
            }
            if (EPI == 2) {
                o0 = 0.5f * o0 * (1.0f + erff(o0 * 0.70710678118654752f));
                o1 = 0.5f * o1 * (1.0f + erff(o1 * 0.70710678118654752f));
                o2 = 0.5f * o2 * (1.0f + erff(o2 * 0.70710678118654752f));
                o3 = 0.5f * o3 * (1.0f + erff(o3 * 0.70710678118654752f));
            }
            if (EPI == 3) {
                float2 r0 = *(const float2*)&resid[(size_t)row0 * Nc + colbase + j0];
                float2 r1 = *(const float2*)&resid[(size_t)row1 * Nc + colbase + j0];
                o0 += r0.x; o1 += r0.y; o2 += r1.x; o3 += r1.y;
            }
            if (PERM) {
                int p0 = colbase + (((j0 & 3) << 1) | ((j0 >> 2) & 1));
                int p1 = colbase + (((j1 & 3) << 1) | ((j1 >> 2) & 1));
                C[(size_t)row0 * Nc + p0] = tf32r(o0);
                C[(size_t)row0 * Nc + p1] = tf32r(o1);
                C[(size_t)row1 * Nc + p0] = tf32r(o2);
                C[(size_t)row1 * Nc + p1] = tf32r(o3);
            } else {
                *(float2*)&C[(size_t)row0 * Nc + colbase + j0] = make_float2(o0, o1);
                *(float2*)&C[(size_t)row1 * Nc + colbase + j0] = make_float2(o2, o3);
            }
        }
    }
}

// ---------------- kv-sum: kv[b,h,r,d] = sum_n relu(k.rf)[n,r] * v[n,d] -------
// rf held in registers, 8 rows per sync, float4 smem traffic.
__global__ __launch_bounds__(256) void kvsum_kernel(
    const float* __restrict__ qkv, const float* __restrict__ rf_l,
    float* __restrict__ kvpart, float* __restrict__ kspart)
{
    __shared__ float ksm[8][64];
    __shared__ float vsm[8][64];
    __shared__ float phism[8][64];
    int tid = threadIdx.x;
    int bh = blockIdx.x;
    int b = bh >> 4, h = bh & 15;
    int chunk = blockIdx.y;

    int prow = tid >> 6, pr = tid & 63;   // prow 0..3
    const float* rfh = rf_l + h * (DH_ * R_);
    // rf column pr into registers: rfr[d] = rf[d][pr]
    float rfr[64];
    #pragma unroll
    for (int d = 0; d < 64; d++) rfr[d] = rfh[d * 64 + pr];

    float acc[16];
    #pragma unroll
    for (int j = 0; j < 16; j++) acc[j] = 0.0f;
    int my_r  = tid >> 2;
    int my_d0 = (tid & 3) << 4;
    float kslocal = 0.0f;
    int nbase = chunk * 256;

    for (int gidx = 0; gidx < 32; gidx++) {
        int n0 = nbase + gidx * 8 + prow;
        size_t base0 = ((size_t)(b * N_ + n0)) * (3 * INNER_) + h * DH_;
        size_t base1 = base0 + (size_t)4 * (3 * INNER_);
        ksm[prow    ][pr] = qkv[base0 + INNER_ + pr];
        ksm[prow + 4][pr] = qkv[base1 + INNER_ + pr];
        vsm[prow    ][pr] = qkv[base0 + 2 * INNER_ + pr];
        vsm[prow + 4][pr] = qkv[base1 + 2 * INNER_ + pr];
        __syncthreads();
        float s0 = 0.0f, s1 = 0.0f;
        #pragma unroll
        for (int dc = 0; dc < 16; dc++) {
            float4 k0 = *(const float4*)&ksm[prow    ][dc * 4];
            float4 k1 = *(const float4*)&ksm[prow + 4][dc * 4];
            s0 = fmaf(k0.x, rfr[dc*4+0], s0); s0 = fmaf(k0.y, rfr[dc*4+1], s0);
            s0 = fmaf(k0.z, rfr[dc*4+2], s0); s0 = fmaf(k0.w, rfr[dc*4+3], s0);
            s1 = fmaf(k1.x, rfr[dc*4+0], s1); s1 = fmaf(k1.y, rfr[dc*4+1], s1);
            s1 = fmaf(k1.z, rfr[dc*4+2], s1); s1 = fmaf(k1.w, rfr[dc*4+3], s1);
        }
        s0 = fmaxf(s0, 0.0f); s1 = fmaxf(s1, 0.0f);
        phism[prow    ][pr] = s0;
        phism[prow + 4][pr] = s1;
        kslocal += s0 + s1;
        __syncthreads();
        #pragma unroll
        for (int rr = 0; rr < 8; rr++) {
            float p = phism[rr][my_r];
            float4 v0 = *(const float4*)&vsm[rr][my_d0];
            float4 v1 = *(const float4*)&vsm[rr][my_d0 + 4];
            float4 v2 = *(const float4*)&vsm[rr][my_d0 + 8];
            float4 v3 = *(const float4*)&vsm[rr][my_d0 + 12];
            acc[0]  = fmaf(p, v0.x, acc[0]);  acc[1]  = fmaf(p, v0.y, acc[1]);
            acc[2]  = fmaf(p, v0.z, acc[2]);  acc[3]  = fmaf(p, v0.w, acc[3]);
            acc[4]  = fmaf(p, v1.x, acc[4]);  acc[5]  = fmaf(p, v1.y, acc[5]);
            acc[6]  = fmaf(p, v1.z, acc[6]);  acc[7]  = fmaf(p, v1.w, acc[7]);
            acc[8]  = fmaf(p, v2.x, acc[8]);  acc[9]  = fmaf(p, v2.y, acc[9]);
            acc[10] = fmaf(p, v2.z, acc[10]); acc[11] = fmaf(p, v2.w, acc[11]);
            acc[12] = fmaf(p, v3.x, acc[12]); acc[13] = fmaf(p, v3.y, acc[13]);
            acc[14] = fmaf(p, v3.z, acc[14]); acc[15] = fmaf(p, v3.w, acc[15]);
        }
        __syncthreads();
    }

    float* kvp = kvpart + ((size_t)(bh * 16 + chunk)) * (R_ * DH_);
    #pragma unroll
    for (int j = 0; j < 16; j++) kvp[my_r * 64 + my_d0 + j] = acc[j];

    phism[prow][pr] = kslocal;
    __syncthreads();
    if (tid < 64) {
        float s = phism[0][tid] + phism[1][tid] + phism[2][tid] + phism[3][tid];
        kspart[(bh * 16 + chunk) * R_ + tid] = s;
    }
}

__global__ __launch_bounds__(256) void kvreduce_kernel(
    const float* __restrict__ kvpart, const float* __restrict__ kspart,
    float* __restrict__ kv, float* __restrict__ ks)
{
    int bh = blockIdx.x, tid = threadIdx.x;
    for (int i = tid; i < R_ * DH_; i += 256) {
        float s = 0.0f;
        #pragma unroll
        for (int c = 0; c < 16; c++)
            s += kvpart[((size_t)(bh * 16 + c)) * (R_ * DH_) + i];
        kv[(size_t)bh * (R_ * DH_) + i] = s;
    }
    if (tid < 64) {
        float s = 0.0f;
        #pragma unroll
        for (int c = 0; c < 16; c++) s += kspart[(bh * 16 + c) * R_ + tid];
        ks[bh * R_ + tid] = s;
    }
}

// ---------------- attention out (writes tf32-rounded, k-permuted) ----------
__global__ __launch_bounds__(256) void attnout_kernel(
    const float* __restrict__ qkv, const float* __restrict__ rf_l,
    const float* __restrict__ kv, const float* __restrict__ ksum,
    float* __restrict__ out)
{
    __shared__ float kvT[64 * 68];     // [d][r] padded: stride 68
    __shared__ float kssm[R_];
    __shared__ float qsm[8][64];
    __shared__ float phism[8][64];
    int tid = threadIdx.x;
    int bh = blockIdx.x;
    int b = bh >> 4, h = bh & 15;
    int tile = blockIdx.y;

    int prow = tid >> 6, pr = tid & 63;
    const float* rfh = rf_l + h * (DH_ * R_);
    float rfr[64];
    #pragma unroll
    for (int d = 0; d < 64; d++) rfr[d] = rfh[d * 64 + pr];

    const float* kvg = kv + (size_t)bh * (R_ * DH_);
    for (int i = tid; i < R_ * DH_; i += 256) {
        int r = i >> 6, d = i & 63;
        kvT[d * 68 + r] = kvg[i];
    }
    if (tid < 64) kssm[tid] = ksum[bh * R_ + tid];
    __syncthreads();

    int nbase = tile * 128;
    int cperm = h * DH_ + (pr & ~7) + (((pr & 3) << 1) | ((pr >> 2) & 1));

    for (int gidx = 0; gidx < 16; gidx++) {
        int n0 = nbase + gidx * 8 + prow;
        size_t base0 = ((size_t)(b * N_ + n0)) * (3 * INNER_) + h * DH_;
        size_t base1 = base0 + (size_t)4 * (3 * INNER_);
        qsm[prow    ][pr] = qkv[base0 + pr];
        qsm[prow + 4][pr] = qkv[base1 + pr];
        __syncthreads();
        float s0 = 0.0f, s1 = 0.0f;
        #pragma unroll
        for (int dc = 0; dc < 16; dc++) {
            float4 q0 = *(const float4*)&qsm[prow    ][dc * 4];
            float4 q1 = *(const float4*)&qsm[prow + 4][dc * 4];
            s0 = fmaf(q0.x, rfr[dc*4+0], s0); s0 = fmaf(q0.y, rfr[dc*4+1], s0);
            s0 = fmaf(q0.z, rfr[dc*4+2], s0); s0 = fmaf(q0.w, rfr[dc*4+3], s0);
            s1 = fmaf(q1.x, rfr[dc*4+0], s1); s1 = fmaf(q1.y, rfr[dc*4+1], s1);
            s1 = fmaf(q1.z, rfr[dc*4+2], s1); s1 = fmaf(q1.w, rfr[dc*4+3], s1);
        }
        phism[prow    ][pr] = fmaxf(s0, 0.0f);
        phism[prow + 4][pr] = fmaxf(s1, 0.0f);
        __syncthreads();
        // out(n, d=pr) = sum_r phi(n,r) * kvT[pr][r]; nz = sum_r phi*kss
        float a0 = 0.0f, a1 = 0.0f, z0 = 0.0f, z1 = 0.0f;
        #pragma unroll
        for (int rc = 0; rc < 16; rc++) {
            float4 p0 = *(const float4*)&phism[prow    ][rc * 4];
            float4 p1 = *(const float4*)&phism[prow + 4][rc * 4];
            float4 kk = *(const float4*)&kvT[pr * 68 + rc * 4];
            float4 ss = *(const float4*)&kssm[rc * 4];
            a0 = fmaf(p0.x, kk.x, a0); a0 = fmaf(p0.y, kk.y, a0);
            a0 = fmaf(p0.z, kk.z, a0); a0 = fmaf(p0.w, kk.w, a0);
            z0 = fmaf(p0.x, ss.x, z0); z0 = fmaf(p0.y, ss.y, z0);
            z0 = fmaf(p0.z, ss.z, z0); z0 = fmaf(p0.w, ss.w, z0);
            a1 = fmaf(p1.x, kk.x, a1); a1 = fmaf(p1.y, kk.y, a1);
            a1 = fmaf(p1.z, kk.z, a1); a1 = fmaf(p1.w, kk.w, a1);
            z1 = fmaf(p1.x, ss.x, z1); z1 = fmaf(p1.y, ss.y, z1);
            z1 = fmaf(p1.z, ss.z, z1); z1 = fmaf(p1.w, ss.w, z1);
        }
        out[((size_t)(b * N_ + n0    )) * INNER_ + cperm] = tf32r(a0 / (z0 + STAB_));
        out[((size_t)(b * N_ + n0 + 4)) * INNER_ + cperm] = tf32r(a1 / (z1 + STAB_));
        __syncthreads();
    }
}

// ---------------- host driver ----------------
extern "C" void kernel_launch(void* const* d_in, const int* in_sizes, int n_in,
                              void* d_out, int out_size)
{
    const int*   tokens  = (const int*)  d_in[0];
    const float* tok_emb = (const float*)d_in[1];
    const float* pos_emb = (const float*)d_in[2];
    const float* Wqkv    = (const float*)d_in[3];
    const float* Wout    = (const float*)d_in[4];
    const float* bout    = (const float*)d_in[5];
    const float* ln1g    = (const float*)d_in[6];
    const float* ln1b    = (const float*)d_in[7];
    const float* ln2g    = (const float*)d_in[8];
    const float* ln2b    = (const float*)d_in[9];
    const float* W1      = (const float*)d_in[10];
    const float* b1      = (const float*)d_in[11];
    const float* W2      = (const float*)d_in[12];
    const float* b2      = (const float*)d_in[13];
    const float* rf      = (const float*)d_in[14];
    float* x = (float*)d_out;

    float *qkv, *ff1, *attnout, *ln, *kvpart, *kspart, *kv, *ksum;
    float *Wqkvp, *Woutp, *W1p, *W2p;
    cudaGetSymbolAddress((void**)&qkv,     g_qkv);
    cudaGetSymbolAddress((void**)&ff1,     g_ff1);
    cudaGetSymbolAddress((void**)&attnout, g_attnout);
    cudaGetSymbolAddress((void**)&ln,      g_ln);
    cudaGetSymbolAddress((void**)&kvpart,  g_kvpart);
    cudaGetSymbolAddress((void**)&kspart,  g_kspart);
    cudaGetSymbolAddress((void**)&kv,      g_kv);
    cudaGetSymbolAddress((void**)&ksum,    g_ksum);
    cudaGetSymbolAddress((void**)&Wqkvp,   g_Wqkvp);
    cudaGetSymbolAddress((void**)&Woutp,   g_Woutp);
    cudaGetSymbolAddress((void**)&W1p,     g_W1p);
    cudaGetSymbolAddress((void**)&W2p,     g_W2p);

    // weight convert: tf32-round + k-permute
    {
        int n8;
        n8 = L_*3*INNER_*D_ / 8; wconv_kernel<<<(n8+255)/256, 256>>>(Wqkv, Wqkvp, n8);
        n8 = L_*D_*INNER_   / 8; wconv_kernel<<<(n8+255)/256, 256>>>(Wout, Woutp, n8);
        n8 = L_*FF_*D_      / 8; wconv_kernel<<<(n8+255)/256, 256>>>(W1,   W1p,   n8);
        n8 = L_*D_*FF_      / 8; wconv_kernel<<<(n8+255)/256, 256>>>(W2,   W2p,   n8);
    }

    embed_kernel<<<M_, 256>>>(tokens, tok_emb, pos_emb, x);

    for (int l = 0; l < L_; l++) {
        const float* Wqkv_l = Wqkvp + (size_t)l * 3 * INNER_ * D_;
        const float* Wout_l = Woutp + (size_t)l * D_ * INNER_;
        const float* bout_l = bout + (size_t)l * D_;
        const float* ln1g_l = ln1g + (size_t)l * D_;
        const float* ln1b_l = ln1b + (size_t)l * D_;
        const float* ln2g_l = ln2g + (size_t)l * D_;
        const float* ln2b_l = ln2b + (size_t)l * D_;
        const float* W1_l   = W1p  + (size_t)l * FF_ * D_;
        const float* b1_l   = b1   + (size_t)l * FF_;
        const float* W2_l   = W2p  + (size_t)l * D_ * FF_;
        const float* b2_l   = b2   + (size_t)l * D_;
        const float* rf_l   = rf   + (size_t)l * H_ * DH_ * R_;

        // --- attention block ---
        ln_kernel<<<M_, 256>>>(x, ln1g_l, ln1b_l, ln);
        gemm_tc<0, false><<<dim3(3 * INNER_ / 128, M_ / 128), 256>>>(
            ln, Wqkv_l, qkv, M_, 3 * INNER_, D_, nullptr, nullptr);
        kvsum_kernel<<<dim3(B_ * H_, 16), 256>>>(qkv, rf_l, kvpart, kspart);
        kvreduce_kernel<<<B_ * H_, 256>>>(kvpart, kspart, kv, ksum);
        attnout_kernel<<<dim3(B_ * H_, N_ / 128), 256>>>(qkv, rf_l, kv, ksum, attnout);
        gemm_tc<3, false><<<dim3(D_ / 128, M_ / 128), 256>>>(
            attnout, Wout_l, x, M_, D_, INNER_, bout_l, x);

        // --- FFN block ---
        ln_kernel<<<M_, 256>>>(x, ln2g_l, ln2b_l, ln);
        gemm_tc<2, true><<<dim3(FF_ / 128, M_ / 128), 256>>>(
            ln, W1_l, ff1, M_, FF_, D_, b1_l, nullptr);
        gemm_tc<3, false><<<dim3(D_ / 128, M_ / 128), 256>>>(
            ff1, W2_l, x, M_, D_, FF_, b2_l, x);
    }
}

// round 11
// speedup vs baseline: 4.7330x; 1.5221x over previous
#include <cuda_runtime.h>
#include <cuda_fp16.h>
#include <math.h>
#include <stdint.h>

// ---------------- problem constants ----------------
#define B_   2
#define N_   4096
#define D_   1024
#define H_   16
#define DH_  64
#define R_   64
#define L_   6
#define FF_  4096
#define INNER_ 1024
#define M_   (B_*N_)        // 8192 rows
#define EPS_ 1e-5f
#define STAB_ 1e-6f

// ---------------- scratch (static device globals; allowed) ----------------
__device__ __align__(16) float  g_qkv[M_ * 3 * INNER_];    // fp32 (attention reads)
__device__ __align__(16) __half g_ff1[M_ * FF_];           // half
__device__ __align__(16) __half g_attnout[M_ * INNER_];    // half
__device__ __align__(16) __half g_ln[M_ * D_];             // half
__device__ __align__(16) float  g_kvpart[B_*H_*16*R_*DH_];
__device__ __align__(16) float  g_kspart[B_*H_*16*R_];
__device__ __align__(16) float  g_kv[B_*H_*R_*DH_];
__device__ __align__(16) float  g_ksum[B_*H_*R_];
// fp16 weight copies (K-major)
__device__ __align__(16) __half g_Wqkvp[L_*3*INNER_*D_];
__device__ __align__(16) __half g_Woutp[L_*D_*INNER_];
__device__ __align__(16) __half g_W1p  [L_*FF_*D_];
__device__ __align__(16) __half g_W2p  [L_*D_*FF_];

// ---------------- helpers ----------------
__device__ __forceinline__ uint32_t smem_u32(const void* p) {
    uint32_t a;
    asm("{ .reg .u64 t; cvta.to.shared.u64 t, %1; cvt.u32.u64 %0, t; }" : "=r"(a) : "l"(p));
    return a;
}
__device__ __forceinline__ void cp16(uint32_t s, const void* g) {
    asm volatile("cp.async.cg.shared.global [%0], [%1], 16;\n" :: "r"(s), "l"(g));
}
#define LDSM_X4(r, addr) \
    asm volatile("ldmatrix.sync.aligned.m8n8.x4.shared.b16 {%0,%1,%2,%3}, [%4];" \
        : "=r"((r)[0]), "=r"((r)[1]), "=r"((r)[2]), "=r"((r)[3]) : "r"(addr))

// ---------------- FP16 tensor-core GEMM, 128x128 tile, k-chunk 32 -----------
// C[M,Nc] = A[M,K] @ Bw[Nc,K]^T  (+ epilogue)
// EPI: 0 = none, 2 = bias+GELU, 3 = bias+residual(fp32).
// OUTH: write half (next GEMM's A) vs float.
#define KC    32          // k-chunk in halves
#define RSTR  40          // row stride in halves (80B) -> conflict-free ldmatrix
#define STAGEB (128 * RSTR * 2)   // bytes per tile stage

template<int EPI, bool OUTH>
__global__ __launch_bounds__(256) void gemm_fp16(
    const __half* __restrict__ A, const __half* __restrict__ Bw,
    void* __restrict__ Cv, int M, int Nc, int K,
    const float* __restrict__ bias, const float* __restrict__ resid)
{
    __shared__ __align__(16) __half sh[2][2][128 * RSTR];
    const uint32_t sbase = smem_u32(&sh[0][0][0]);

    const int tid  = threadIdx.x;
    const int bm0  = blockIdx.y * 128;
    const int bn0  = blockIdx.x * 128;
    const int warp = tid >> 5;
    const int lane = tid & 31;
    const int wm   = warp >> 2;     // 0..1 -> 64-row slab
    const int wn   = warp & 3;      // 0..3 -> 32-col slab
    const int g8   = lane >> 2;     // 0..7 (c-frag row group)
    const int qid  = lane & 3;

    float c[4][4][4];
    #pragma unroll
    for (int mi = 0; mi < 4; mi++)
        #pragma unroll
        for (int ni = 0; ni < 4; ni++)
            #pragma unroll
            for (int j = 0; j < 4; j++) c[mi][ni][j] = 0.0f;

    const int nIter = K / KC;

    auto load_stage = [&](int it, int buf) {
        const int k0 = it * KC;
        uint32_t sA = sbase + buf * 2 * STAGEB;
        uint32_t sB = sA + STAGEB;
        #pragma unroll
        for (int i = 0; i < 2; i++) {
            int f = i * 256 + tid;          // 0..511
            int row = f >> 2, seg = f & 3;  // seg: 8-half (16B) segment
            cp16(sA + (row * RSTR + seg * 8) * 2,
                 &A[(size_t)(bm0 + row) * K + k0 + seg * 8]);
        }
        #pragma unroll
        for (int i = 0; i < 2; i++) {
            int f = i * 256 + tid;
            int row = f >> 2, seg = f & 3;
            cp16(sB + (row * RSTR + seg * 8) * 2,
                 &Bw[(size_t)(bn0 + row) * K + k0 + seg * 8]);
        }
        asm volatile("cp.async.commit_group;\n" ::: "memory");
    };

    load_stage(0, 0);

    for (int it = 0; it < nIter; it++) {
        int buf = it & 1;
        if (it + 1 < nIter) {
            load_stage(it + 1, buf ^ 1);
            asm volatile("cp.async.wait_group 1;\n" ::: "memory");
        } else {
            asm volatile("cp.async.wait_group 0;\n" ::: "memory");
        }
        __syncthreads();

        uint32_t sA = sbase + buf * 2 * STAGEB;
        uint32_t sB = sA + STAGEB;

        #pragma unroll
        for (int ks = 0; ks < KC; ks += 16) {
            uint32_t af[4][4];
            #pragma unroll
            for (int mi = 0; mi < 4; mi++) {
                int m0 = wm * 64 + mi * 16;
                // lanes 0-15: rows m0+lane&15 @k=ks ; lanes 16-31: same rows @k=ks+8
                uint32_t addr = sA + (((m0 + (lane & 15)) * RSTR) + ks + ((lane >> 4) << 3)) * 2;
                LDSM_X4(af[mi], addr);
            }
            uint32_t bf[2][4];
            #pragma unroll
            for (int nb = 0; nb < 2; nb++) {
                int n0 = wn * 32 + nb * 16;
                // lanes 0-7: rows n0+0..7 @ks ; 8-15: n0+0..7 @ks+8 ;
                // 16-23: n0+8..15 @ks ; 24-31: n0+8..15 @ks+8
                uint32_t addr = sB + (((n0 + (lane & 7) + ((lane >> 4) << 3)) * RSTR)
                                      + ks + (((lane >> 3) & 1) << 3)) * 2;
                LDSM_X4(bf[nb], addr);
            }
            #pragma unroll
            for (int mi = 0; mi < 4; mi++)
                #pragma unroll
                for (int ni = 0; ni < 4; ni++) {
                    uint32_t b0 = bf[ni >> 1][(ni & 1) * 2];
                    uint32_t b1 = bf[ni >> 1][(ni & 1) * 2 + 1];
                    asm volatile(
                        "mma.sync.aligned.m16n8k16.row.col.f32.f16.f16.f32 "
                        "{%0,%1,%2,%3}, {%4,%5,%6,%7}, {%8,%9}, {%0,%1,%2,%3};\n"
                        : "+f"(c[mi][ni][0]), "+f"(c[mi][ni][1]),
                          "+f"(c[mi][ni][2]), "+f"(c[mi][ni][3])
                        : "r"(af[mi][0]), "r"(af[mi][1]), "r"(af[mi][2]), "r"(af[mi][3]),
                          "r"(b0), "r"(b1));
                }
        }
        __syncthreads();
    }

    // ---- epilogue ----
    #pragma unroll
    for (int mi = 0; mi < 4; mi++) {
        int row0 = bm0 + wm * 64 + mi * 16 + g8;
        int row1 = row0 + 8;
        #pragma unroll
        for (int ni = 0; ni < 4; ni++) {
            int col = bn0 + wn * 32 + ni * 8 + qid * 2;
            float o0 = c[mi][ni][0], o1 = c[mi][ni][1];
            float o2 = c[mi][ni][2], o3 = c[mi][ni][3];
            if (EPI >= 1) {
                float b0 = bias[col], b1 = bias[col + 1];
                o0 += b0; o1 += b1; o2 += b0; o3 += b1;
            }
            if (EPI == 2) {
                o0 = 0.5f * o0 * (1.0f + erff(o0 * 0.70710678118654752f));
                o1 = 0.5f * o1 * (1.0f + erff(o1 * 0.70710678118654752f));
                o2 = 0.5f * o2 * (1.0f + erff(o2 * 0.70710678118654752f));
                o3 = 0.5f * o3 * (1.0f + erff(o3 * 0.70710678118654752f));
            }
            if (EPI == 3) {
                float2 r0 = *(const float2*)&resid[(size_t)row0 * Nc + col];
                float2 r1 = *(const float2*)&resid[(size_t)row1 * Nc + col];
                o0 += r0.x; o1 += r0.y; o2 += r1.x; o3 += r1.y;
            }
            if (OUTH) {
                __half* C = (__half*)Cv;
                *(__half2*)&C[(size_t)row0 * Nc + col] = __floats2half2_rn(o0, o1);
                *(__half2*)&C[(size_t)row1 * Nc + col] = __floats2half2_rn(o2, o3);
            } else {
                float* C = (float*)Cv;
                *(float2*)&C[(size_t)row0 * Nc + col] = make_float2(o0, o1);
                *(float2*)&C[(size_t)row1 * Nc + col] = make_float2(o2, o3);
            }
        }
    }
}

// ---------------- weight convert: fp32 -> fp16 ----------------
__global__ __launch_bounds__(256) void wconv_kernel(
    const float* __restrict__ in, __half* __restrict__ out, int n4)
{
    int i = blockIdx.x * 256 + threadIdx.x;
    if (i >= n4) return;
    float4 v = *(const float4*)&in[(size_t)i * 4];
    __half2 h0 = __floats2half2_rn(v.x, v.y);
    __half2 h1 = __floats2half2_rn(v.z, v.w);
    *(__half2*)&out[(size_t)i * 4]     = h0;
    *(__half2*)&out[(size_t)i * 4 + 2] = h1;
}

// ---------------- embedding ----------------
__global__ __launch_bounds__(256) void embed_kernel(
    const int* __restrict__ tokens, const float* __restrict__ te,
    const float* __restrict__ pe, float* __restrict__ x)
{
    int row = blockIdx.x;
    int tid = threadIdx.x;
    int n = row & (N_ - 1);
    int tok = tokens[row];
    float4 a = *(const float4*)&te[(size_t)tok * D_ + tid * 4];
    float4 p = *(const float4*)&pe[(size_t)n * D_ + tid * 4];
    a.x += p.x; a.y += p.y; a.z += p.z; a.w += p.w;
    *(float4*)&x[(size_t)row * D_ + tid * 4] = a;
}

// ---------------- fused LayerNorm (stats + apply -> fp16) -------------------
__global__ __launch_bounds__(256) void ln_kernel(
    const float* __restrict__ x, const float* __restrict__ lng,
    const float* __restrict__ lnb, __half* __restrict__ h)
{
    __shared__ float red[256];
    int row = blockIdx.x, tid = threadIdx.x;
    float4 v = *(const float4*)&x[(size_t)row * D_ + tid * 4];
    red[tid] = v.x + v.y + v.z + v.w; __syncthreads();
    #pragma unroll
    for (int o = 128; o > 0; o >>= 1) { if (tid < o) red[tid] += red[tid + o]; __syncthreads(); }
    float mu = red[0] * (1.0f / D_);
    __syncthreads();
    float dx = v.x - mu, dy = v.y - mu, dz = v.z - mu, dw = v.w - mu;
    red[tid] = dx*dx + dy*dy + dz*dz + dw*dw; __syncthreads();
    #pragma unroll
    for (int o = 128; o > 0; o >>= 1) { if (tid < o) red[tid] += red[tid + o]; __syncthreads(); }
    float rs = rsqrtf(red[0] * (1.0f / D_) + EPS_);
    float4 gg = *(const float4*)&lng[tid * 4];
    float4 bb = *(const float4*)&lnb[tid * 4];
    __half2 h0 = __floats2half2_rn(dx * rs * gg.x + bb.x, dy * rs * gg.y + bb.y);
    __half2 h1 = __floats2half2_rn(dz * rs * gg.z + bb.z, dw * rs * gg.w + bb.w);
    __half* hr = h + (size_t)row * D_ + tid * 4;
    *(__half2*)&hr[0] = h0;
    *(__half2*)&hr[2] = h1;
}

// ---------------- kv-sum ----------------
__global__ __launch_bounds__(256) void kvsum_kernel(
    const float* __restrict__ qkv, const float* __restrict__ rf_l,
    float* __restrict__ kvpart, float* __restrict__ kspart)
{
    __shared__ float ksm[8][64];
    __shared__ float vsm[8][64];
    __shared__ float phism[8][64];
    int tid = threadIdx.x;
    int bh = blockIdx.x;
    int b = bh >> 4, h = bh & 15;
    int chunk = blockIdx.y;

    int prow = tid >> 6, pr = tid & 63;
    const float* rfh = rf_l + h * (DH_ * R_);
    float rfr[64];
    #pragma unroll
    for (int d = 0; d < 64; d++) rfr[d] = rfh[d * 64 + pr];

    float acc[16];
    #pragma unroll
    for (int j = 0; j < 16; j++) acc[j] = 0.0f;
    int my_r  = tid >> 2;
    int my_d0 = (tid & 3) << 4;
    float kslocal = 0.0f;
    int nbase = chunk * 256;

    for (int gidx = 0; gidx < 32; gidx++) {
        int n0 = nbase + gidx * 8 + prow;
        size_t base0 = ((size_t)(b * N_ + n0)) * (3 * INNER_) + h * DH_;
        size_t base1 = base0 + (size_t)4 * (3 * INNER_);
        ksm[prow    ][pr] = qkv[base0 + INNER_ + pr];
        ksm[prow + 4][pr] = qkv[base1 + INNER_ + pr];
        vsm[prow    ][pr] = qkv[base0 + 2 * INNER_ + pr];
        vsm[prow + 4][pr] = qkv[base1 + 2 * INNER_ + pr];
        __syncthreads();
        float s0 = 0.0f, s1 = 0.0f;
        #pragma unroll
        for (int dc = 0; dc < 16; dc++) {
            float4 k0 = *(const float4*)&ksm[prow    ][dc * 4];
            float4 k1 = *(const float4*)&ksm[prow + 4][dc * 4];
            s0 = fmaf(k0.x, rfr[dc*4+0], s0); s0 = fmaf(k0.y, rfr[dc*4+1], s0);
            s0 = fmaf(k0.z, rfr[dc*4+2], s0); s0 = fmaf(k0.w, rfr[dc*4+3], s0);
            s1 = fmaf(k1.x, rfr[dc*4+0], s1); s1 = fmaf(k1.y, rfr[dc*4+1], s1);
            s1 = fmaf(k1.z, rfr[dc*4+2], s1); s1 = fmaf(k1.w, rfr[dc*4+3], s1);
        }
        s0 = fmaxf(s0, 0.0f); s1 = fmaxf(s1, 0.0f);
        phism[prow    ][pr] = s0;
        phism[prow + 4][pr] = s1;
        kslocal += s0 + s1;
        __syncthreads();
        #pragma unroll
        for (int rr = 0; rr < 8; rr++) {
            float p = phism[rr][my_r];
            float4 v0 = *(const float4*)&vsm[rr][my_d0];
            float4 v1 = *(const float4*)&vsm[rr][my_d0 + 4];
            float4 v2 = *(const float4*)&vsm[rr][my_d0 + 8];
            float4 v3 = *(const float4*)&vsm[rr][my_d0 + 12];
            acc[0]  = fmaf(p, v0.x, acc[0]);  acc[1]  = fmaf(p, v0.y, acc[1]);
            acc[2]  = fmaf(p, v0.z, acc[2]);  acc[3]  = fmaf(p, v0.w, acc[3]);
            acc[4]  = fmaf(p, v1.x, acc[4]);  acc[5]  = fmaf(p, v1.y, acc[5]);
            acc[6]  = fmaf(p, v1.z, acc[6]);  acc[7]  = fmaf(p, v1.w, acc[7]);
            acc[8]  = fmaf(p, v2.x, acc[8]);  acc[9]  = fmaf(p, v2.y, acc[9]);
            acc[10] = fmaf(p, v2.z, acc[10]); acc[11] = fmaf(p, v2.w, acc[11]);
            acc[12] = fmaf(p, v3.x, acc[12]); acc[13] = fmaf(p, v3.y, acc[13]);
            acc[14] = fmaf(p, v3.z, acc[14]); acc[15] = fmaf(p, v3.w, acc[15]);
        }
        __syncthreads();
    }

    float* kvp = kvpart + ((size_t)(bh * 16 + chunk)) * (R_ * DH_);
    #pragma unroll
    for (int j = 0; j < 16; j++) kvp[my_r * 64 + my_d0 + j] = acc[j];

    phism[prow][pr] = kslocal;
    __syncthreads();
    if (tid < 64) {
        float s = phism[0][tid] + phism[1][tid] + phism[2][tid] + phism[3][tid];
        kspart[(bh * 16 + chunk) * R_ + tid] = s;
    }
}

__global__ __launch_bounds__(256) void kvreduce_kernel(
    const float* __restrict__ kvpart, const float* __restrict__ kspart,
    float* __restrict__ kv, float* __restrict__ ks)
{
    int bh = blockIdx.x, tid = threadIdx.x;
    for (int i = tid; i < R_ * DH_; i += 256) {
        float s = 0.0f;
        #pragma unroll
        for (int c = 0; c < 16; c++)
            s += kvpart[((size_t)(bh * 16 + c)) * (R_ * DH_) + i];
        kv[(size_t)bh * (R_ * DH_) + i] = s;
    }
    if (tid < 64) {
        float s = 0.0f;
        #pragma unroll
        for (int c = 0; c < 16; c++) s += kspart[(bh * 16 + c) * R_ + tid];
        ks[bh * R_ + tid] = s;
    }
}

// ---------------- attention out (writes fp16) ----------------
__global__ __launch_bounds__(256) void attnout_kernel(
    const float* __restrict__ qkv, const float* __restrict__ rf_l,
    const float* __restrict__ kv, const float* __restrict__ ksum,
    __half* __restrict__ out)
{
    __shared__ float kvT[64 * 68];
    __shared__ float kssm[R_];
    __shared__ float qsm[8][64];
    __shared__ float phism[8][64];
    int tid = threadIdx.x;
    int bh = blockIdx.x;
    int b = bh >> 4, h = bh & 15;
    int tile = blockIdx.y;

    int prow = tid >> 6, pr = tid & 63;
    const float* rfh = rf_l + h * (DH_ * R_);
    float rfr[64];
    #pragma unroll
    for (int d = 0; d < 64; d++) rfr[d] = rfh[d * 64 + pr];

    const float* kvg = kv + (size_t)bh * (R_ * DH_);
    for (int i = tid; i < R_ * DH_; i += 256) {
        int r = i >> 6, d = i & 63;
        kvT[d * 68 + r] = kvg[i];
    }
    if (tid < 64) kssm[tid] = ksum[bh * R_ + tid];
    __syncthreads();

    int nbase = tile * 128;
    for (int gidx = 0; gidx < 16; gidx++) {
        int n0 = nbase + gidx * 8 + prow;
        size_t base0 = ((size_t)(b * N_ + n0)) * (3 * INNER_) + h * DH_;
        size_t base1 = base0 + (size_t)4 * (3 * INNER_);
        qsm[prow    ][pr] = qkv[base0 + pr];
        qsm[prow + 4][pr] = qkv[base1 + pr];
        __syncthreads();
        float s0 = 0.0f, s1 = 0.0f;
        #pragma unroll
        for (int dc = 0; dc < 16; dc++) {
            float4 q0 = *(const float4*)&qsm[prow    ][dc * 4];
            float4 q1 = *(const float4*)&qsm[prow + 4][dc * 4];
            s0 = fmaf(q0.x, rfr[dc*4+0], s0); s0 = fmaf(q0.y, rfr[dc*4+1], s0);
            s0 = fmaf(q0.z, rfr[dc*4+2], s0); s0 = fmaf(q0.w, rfr[dc*4+3], s0);
            s1 = fmaf(q1.x, rfr[dc*4+0], s1); s1 = fmaf(q1.y, rfr[dc*4+1], s1);
            s1 = fmaf(q1.z, rfr[dc*4+2], s1); s1 = fmaf(q1.w, rfr[dc*4+3], s1);
        }
        phism[prow    ][pr] = fmaxf(s0, 0.0f);
        phism[prow + 4][pr] = fmaxf(s1, 0.0f);
        __syncthreads();
        float a0 = 0.0f, a1 = 0.0f, z0 = 0.0f, z1 = 0.0f;
        #pragma unroll
        for (int rc = 0; rc < 16; rc++) {
            float4 p0 = *(const float4*)&phism[prow    ][rc * 4];
            float4 p1 = *(const float4*)&phism[prow + 4][rc * 4];
            float4 kk = *(const float4*)&kvT[pr * 68 + rc * 4];
            float4 ss = *(const float4*)&kssm[rc * 4];
            a0 = fmaf(p0.x, kk.x, a0); a0 = fmaf(p0.y, kk.y, a0);
            a0 = fmaf(p0.z, kk.z, a0); a0 = fmaf(p0.w, kk.w, a0);
            z0 = fmaf(p0.x, ss.x, z0); z0 = fmaf(p0.y, ss.y, z0);
            z0 = fmaf(p0.z, ss.z, z0); z0 = fmaf(p0.w, ss.w, z0);
            a1 = fmaf(p1.x, kk.x, a1); a1 = fmaf(p1.y, kk.y, a1);
            a1 = fmaf(p1.z, kk.z, a1); a1 = fmaf(p1.w, kk.w, a1);
            z1 = fmaf(p1.x, ss.x, z1); z1 = fmaf(p1.y, ss.y, z1);
            z1 = fmaf(p1.z, ss.z, z1); z1 = fmaf(p1.w, ss.w, z1);
        }
        out[((size_t)(b * N_ + n0    )) * INNER_ + h * DH_ + pr] = __float2half_rn(a0 / (z0 + STAB_));
        out[((size_t)(b * N_ + n0 + 4)) * INNER_ + h * DH_ + pr] = __float2half_rn(a1 / (z1 + STAB_));
        __syncthreads();
    }
}

// ---------------- host driver ----------------
extern "C" void kernel_launch(void* const* d_in, const int* in_sizes, int n_in,
                              void* d_out, int out_size)
{
    const int*   tokens  = (const int*)  d_in[0];
    const float* tok_emb = (const float*)d_in[1];
    const float* pos_emb = (const float*)d_in[2];
    const float* Wqkv    = (const float*)d_in[3];
    const float* Wout    = (const float*)d_in[4];
    const float* bout    = (const float*)d_in[5];
    const float* ln1g    = (const float*)d_in[6];
    const float* ln1b    = (const float*)d_in[7];
    const float* ln2g    = (const float*)d_in[8];
    const float* ln2b    = (const float*)d_in[9];
    const float* W1      = (const float*)d_in[10];
    const float* b1      = (const float*)d_in[11];
    const float* W2      = (const float*)d_in[12];
    const float* b2      = (const float*)d_in[13];
    const float* rf      = (const float*)d_in[14];
    float* x = (float*)d_out;

    float *qkv, *kvpart, *kspart, *kv, *ksum;
    __half *ff1, *attnout, *ln, *Wqkvp, *Woutp, *W1p, *W2p;
    cudaGetSymbolAddress((void**)&qkv,     g_qkv);
    cudaGetSymbolAddress((void**)&ff1,     g_ff1);
    cudaGetSymbolAddress((void**)&attnout, g_attnout);
    cudaGetSymbolAddress((void**)&ln,      g_ln);
    cudaGetSymbolAddress((void**)&kvpart,  g_kvpart);
    cudaGetSymbolAddress((void**)&kspart,  g_kspart);
    cudaGetSymbolAddress((void**)&kv,      g_kv);
    cudaGetSymbolAddress((void**)&ksum,    g_ksum);
    cudaGetSymbolAddress((void**)&Wqkvp,   g_Wqkvp);
    cudaGetSymbolAddress((void**)&Woutp,   g_Woutp);
    cudaGetSymbolAddress((void**)&W1p,     g_W1p);
    cudaGetSymbolAddress((void**)&W2p,     g_W2p);

    // weight convert: fp32 -> fp16
    {
        int n4;
        n4 = L_*3*INNER_*D_ / 4; wconv_kernel<<<(n4+255)/256, 256>>>(Wqkv, Wqkvp, n4);
        n4 = L_*D_*INNER_   / 4; wconv_kernel<<<(n4+255)/256, 256>>>(Wout, Woutp, n4);
        n4 = L_*FF_*D_      / 4; wconv_kernel<<<(n4+255)/256, 256>>>(W1,   W1p,   n4);
        n4 = L_*D_*FF_      / 4; wconv_kernel<<<(n4+255)/256, 256>>>(W2,   W2p,   n4);
    }

    embed_kernel<<<M_, 256>>>(tokens, tok_emb, pos_emb, x);

    for (int l = 0; l < L_; l++) {
        const __half* Wqkv_l = Wqkvp + (size_t)l * 3 * INNER_ * D_;
        const __half* Wout_l = Woutp + (size_t)l * D_ * INNER_;
        const float* bout_l = bout + (size_t)l * D_;
        const float* ln1g_l = ln1g + (size_t)l * D_;
        const float* ln1b_l = ln1b + (size_t)l * D_;
        const float* ln2g_l = ln2g + (size_t)l * D_;
        const float* ln2b_l = ln2b + (size_t)l * D_;
        const __half* W1_l  = W1p  + (size_t)l * FF_ * D_;
        const float* b1_l   = b1   + (size_t)l * FF_;
        const __half* W2_l  = W2p  + (size_t)l * D_ * FF_;
        const float* b2_l   = b2   + (size_t)l * D_;
        const float* rf_l   = rf   + (size_t)l * H_ * DH_ * R_;

        // --- attention block ---
        ln_kernel<<<M_, 256>>>(x, ln1g_l, ln1b_l, ln);
        gemm_fp16<0, false><<<dim3(3 * INNER_ / 128, M_ / 128), 256>>>(
            ln, Wqkv_l, qkv, M_, 3 * INNER_, D_, nullptr, nullptr);
        kvsum_kernel<<<dim3(B_ * H_, 16), 256>>>(qkv, rf_l, kvpart, kspart);
        kvreduce_kernel<<<B_ * H_, 256>>>(kvpart, kspart, kv, ksum);
        attnout_kernel<<<dim3(B_ * H_, N_ / 128), 256>>>(qkv, rf_l, kv, ksum, attnout);
        gemm_fp16<3, false><<<dim3(D_ / 128, M_ / 128), 256>>>(
            attnout, Wout_l, x, M_, D_, INNER_, bout_l, x);

        // --- FFN block ---
        ln_kernel<<<M_, 256>>>(x, ln2g_l, ln2b_l, ln);
        gemm_fp16<2, true><<<dim3(FF_ / 128, M_ / 128), 256>>>(
            ln, W1_l, ff1, M_, FF_, D_, b1_l, nullptr);
        gemm_fp16<3, false><<<dim3(D_ / 128, M_ / 128), 256>>>(
            ff1, W2_l, x, M_, D_, FF_, b2_l, x);
    }
}